// round 16
// baseline (speedup 1.0000x reference)
#include <cuda_runtime.h>
#include <cuda_fp16.h>
#include <cstdint>
#include <cstddef>

#define SEQ     4096
#define DMODEL  2048
#define DH      128
#define CHUNK   512          // keys per split-KV work unit
#define MAXC    8            // max chunks per q-tile (4096/512)

// Scratch (allocation-free rule: __device__ globals)
__device__ __align__(16) __half g_Qh[SEQ * DH];          // [row][col]
__device__ __align__(16) __half g_Kh[SEQ * DH];          // [row][col]
__device__ __align__(16) __half g_Vh[SEQ * DH];          // [tile32][col][key-in-tile]
// W as fp16 m16n8k16 b-fragment pairs:
// [mat][kb16 0..127][n 0..127][t4 0..3][2]  (u32 = half2 units)
__device__ __align__(16) uint32_t g_Whf[3 * 128 * 128 * 8];
// split-KV partials
__device__ float g_Opart[64 * MAXC * 64 * DH];
__device__ float g_mpart[64 * MAXC * 64];
__device__ float g_lpart[64 * MAXC * 64];
// per-qt completion counters (zero-init; reset to 0 by the combining CTA)
__device__ int g_cnt[64];

__device__ __forceinline__ float ex2(float x) {
    float y;
    asm("ex2.approx.ftz.f32 %0, %1;" : "=f"(y) : "f"(x));
    return y;
}
__device__ __forceinline__ void mma_f16(float d[4], const uint32_t a[4],
                                        uint32_t b0, uint32_t b1) {
    asm volatile(
        "mma.sync.aligned.m16n8k16.row.col.f32.f16.f16.f32 "
        "{%0,%1,%2,%3},{%4,%5,%6,%7},{%8,%9},{%0,%1,%2,%3};\n"
        : "+f"(d[0]), "+f"(d[1]), "+f"(d[2]), "+f"(d[3])
        : "r"(a[0]), "r"(a[1]), "r"(a[2]), "r"(a[3]), "r"(b0), "r"(b1));
}
__device__ __forceinline__ void cpa16(uint32_t dst, const void* src) {
    asm volatile("cp.async.cg.shared.global [%0], [%1], 16;\n" :: "r"(dst), "l"(src));
}
__device__ __forceinline__ void cp_commit() {
    asm volatile("cp.async.commit_group;\n" ::);
}
template <int N>
__device__ __forceinline__ void cp_wait() {
    asm volatile("cp.async.wait_group %0;\n" :: "n"(N));
}
__device__ __forceinline__ uint32_t s2u(const void* p) {
    return (uint32_t)__cvta_generic_to_shared(p);
}
__device__ __forceinline__ uint32_t packh2(float x, float y) {
    __half2 h = __floats2half2_rn(x, y);
    return *(uint32_t*)&h;
}

// ---------------------------------------------------------------------------
// prep_w (unchanged): W -> fp16 k16 b-fragment pairs.
// ---------------------------------------------------------------------------
__global__ __launch_bounds__(256)
void prep_w(const float* __restrict__ wq, const float* __restrict__ wk,
            const float* __restrict__ wv) {
    int id = blockIdx.x * 256 + threadIdx.x;       // 0 .. 196607
    int mat = id / (128 * 128 * 4);
    int rem = id % (128 * 128 * 4);
    int kb = rem >> 9;
    int rem2 = rem & 511;
    int n = rem2 >> 2;
    int t4 = rem2 & 3;
    const float* W = (mat == 0) ? wq : (mat == 1) ? wk : wv;
    const float* wr = W + (size_t)n * DMODEL + kb * 16;
    uint2 o;
    o.x = packh2(wr[2 * t4],     wr[2 * t4 + 1]);
    o.y = packh2(wr[8 + 2 * t4], wr[8 + 2 * t4 + 1]);
    *(uint2*)&g_Whf[(((size_t)mat * 128 + kb) * 128 + n) * 8 + t4 * 2] = o;
}

// ---------------------------------------------------------------------------
// Projection v8: fp16 m16n8k16, full K, fused epilogue — M-tile 32.
// grid (128 mtiles, 3 mats) = 384 CTAs, 128 thr, occ 4 -> balanced waves
// (3/2.6 load ratio vs 2/1.3 at M64). depth-4 cp.async, K-step 16.
// ---------------------------------------------------------------------------
#define PJ_DEPTH 4
#define XSTRH    24                      // fp32 words per X smem row
#define XS_FL    (32 * XSTRH)            // 768 floats / stage
#define WS_U32   (128 * 8)               // 1024 u32 / stage
#define PJ_SMEM  (PJ_DEPTH * (XS_FL * 4 + WS_U32 * 4))   // 28672 B

__global__ __launch_bounds__(128, 4)
void proj_kernel(const float* __restrict__ xq, const float* __restrict__ xk,
                 const float* __restrict__ xv,
                 const float* __restrict__ bq, const float* __restrict__ bk,
                 const float* __restrict__ bv) {
    extern __shared__ float sm[];
    float*    Xs = sm;                                   // [4][32][24]
    uint32_t* Wh = (uint32_t*)(sm + PJ_DEPTH * XS_FL);   // [4][128][8]

    const int mat = blockIdx.y;
    const float* X    = (mat == 0) ? xq : (mat == 1) ? xk : xv;
    const float* bias = (mat == 0) ? bq : (mat == 1) ? bk : bv;

    const int tid  = threadIdx.x;
    const int warp = tid >> 5, lane = tid & 31;
    const int g    = lane >> 2, t4 = lane & 3;
    const int wm   = warp >> 1;   // 0..1 : 16 M-rows each
    const int wn   = warp & 1;    // 0..1 : 64 N-cols each
    const int m0   = blockIdx.x * 32;

    const uint32_t* gwh = g_Whf + (size_t)mat * 128 * 128 * 8;

    float acc[8][4] = {};

    // stage sidx covers K16 group kb = sidx; slot sidx % 4
    auto issue = [&](int sidx) {
        const int s  = sidx & (PJ_DEPTH - 1);
        const int k0 = sidx * 16;
        // X: 32 rows x 16 floats = 128 16B chunks -> 1 per thread
        {
            int r = tid >> 2, c4 = (tid & 3) * 4;
            cpa16(s2u(&Xs[(s * 32 + r) * XSTRH + c4]),
                  X + (size_t)(m0 + r) * DMODEL + k0 + c4);
        }
        // W: 128 n x 8 u32 = 256 16B chunks -> 2 per thread
#pragma unroll
        for (int t = 0; t < 2; ++t) {
            int i = tid + t * 128;
            int n = i >> 1, half = i & 1;
            cpa16(s2u(&Wh[(s * 128 + n) * 8 + half * 4]),
                  gwh + (((size_t)sidx) * 128 + n) * 8 + half * 4);
        }
        cp_commit();
    };

    issue(0); issue(1); issue(2);

    const int NK = DMODEL / 16;   // 128 stages
    for (int i = 0; i < NK; ++i) {
        if (i + 3 < NK) { cp_wait<2>(); } else { cp_wait<0>(); }
        __syncthreads();
        if (i + 3 < NK) issue(i + 3);

        const int s = i & (PJ_DEPTH - 1);
        const float*    Xc = &Xs[s * XS_FL];
        const uint32_t* Wc = &Wh[s * WS_U32];

        uint32_t a[4];
        {
            int r = wm * 16 + g;
            float2 x0 = *(const float2*)&Xc[r * XSTRH + 2 * t4];
            float2 x1 = *(const float2*)&Xc[(r + 8) * XSTRH + 2 * t4];
            float2 x2 = *(const float2*)&Xc[r * XSTRH + 2 * t4 + 8];
            float2 x3 = *(const float2*)&Xc[(r + 8) * XSTRH + 2 * t4 + 8];
            a[0] = packh2(x0.x, x0.y);
            a[1] = packh2(x1.x, x1.y);
            a[2] = packh2(x2.x, x2.y);
            a[3] = packh2(x3.x, x3.y);
        }
#pragma unroll
        for (int nt = 0; nt < 8; ++nt) {
            int n = wn * 64 + nt * 8 + g;
            uint2 b = *(const uint2*)&Wc[n * 8 + t4 * 2];   // LDS.64, conflict-free
            mma_f16(acc[nt], a, b.x, b.y);
        }
    }

    // fused epilogue: bias + fp16; Q/K natural layout, V transposed per tile
    if (mat < 2) {
        __half* dst = (mat == 0) ? g_Qh : g_Kh;
#pragma unroll
        for (int nt = 0; nt < 8; ++nt) {
            int r = m0 + wm * 16 + g;
            int c = wn * 64 + nt * 8 + t4 * 2;
            float b0 = bias[c], b1 = bias[c + 1];
            *(uint32_t*)(dst + (size_t)r * DH + c) =
                packh2(acc[nt][0] + b0, acc[nt][1] + b1);
            *(uint32_t*)(dst + (size_t)(r + 8) * DH + c) =
                packh2(acc[nt][2] + b0, acc[nt][3] + b1);
        }
    } else {
#pragma unroll
        for (int nt = 0; nt < 8; ++nt) {
            int r = m0 + wm * 16 + g;
            int c = wn * 64 + nt * 8 + t4 * 2;
            float b0 = bias[c], b1 = bias[c + 1];
            size_t base = (size_t)(r >> 5) * (DH * 32);
            int lr = r & 31;
            g_Vh[base + (size_t)c * 32 + lr]            = __float2half_rn(acc[nt][0] + b0);
            g_Vh[base + (size_t)(c + 1) * 32 + lr]      = __float2half_rn(acc[nt][1] + b1);
            g_Vh[base + (size_t)c * 32 + lr + 8]        = __float2half_rn(acc[nt][2] + b0);
            g_Vh[base + (size_t)(c + 1) * 32 + lr + 8]  = __float2half_rn(acc[nt][3] + b1);
        }
    }
}

// ---------------------------------------------------------------------------
// Split-KV causal flash attention with FUSED combine: last CTA of each
// multi-chunk q-tile merges the partials (last-block pattern + counter reset
// for graph replay). Mainloop byte-identical to the 83.0 build.
// ---------------------------------------------------------------------------
#define BM 64
#define BN 32

__global__ __launch_bounds__(128, 2)
void attn_kernel(float* __restrict__ out) {
    const int qt = blockIdx.x;
    const int ch = blockIdx.y;
    const int nc = (qt >> 3) + 1;
    if (ch >= nc) return;

    __shared__ uint32_t Ks2[32][68];
    __shared__ uint32_t Vs2[128][20];
    __shared__ uint32_t Ps2[4][16][20];
    __shared__ int isLast;

    const int tid  = threadIdx.x;
    const int warp = tid >> 5, lane = tid & 31;
    const int g    = lane >> 2, t4 = lane & 3;
    const int qm0  = qt * BM;
    const int row_base = qm0 + warp * 16;
    const float NEG_INF = __int_as_float(0xff800000u);
    const float SC = 0.02209708691207961f * 1.4426950408889634f;

    const int kstart = ch * CHUNK;
    const int kend   = min(kstart + CHUNK, qm0 + BM);
    const int ntiles = (kend - kstart) / BN;

    const uint32_t* qh32 = (const uint32_t*)g_Qh;
    uint32_t qf[8][4];
    {
        const int r0 = row_base + g, r1 = r0 + 8;
#pragma unroll
        for (int kt2 = 0; kt2 < 8; ++kt2) {
            qf[kt2][0] = qh32[(size_t)r0 * 64 + kt2 * 8 + t4];
            qf[kt2][1] = qh32[(size_t)r1 * 64 + kt2 * 8 + t4];
            qf[kt2][2] = qh32[(size_t)r0 * 64 + kt2 * 8 + t4 + 4];
            qf[kt2][3] = qh32[(size_t)r1 * 64 + kt2 * 8 + t4 + 4];
        }
    }

    float acc[16][4] = {};
    float m0r = NEG_INF, m1r = NEG_INF;
    float l0 = 0.f, l1 = 0.f;

    for (int j = 0; j < ntiles; ++j) {
        const int n0 = kstart + j * BN;
        const int vtile = n0 >> 5;

#pragma unroll
        for (int t = 0; t < 4; ++t) {
            int i = tid + t * 128;
            int r = i >> 4, grp = i & 15;
            *(uint4*)&Ks2[r][grp * 4] =
                *(const uint4*)(g_Kh + ((size_t)(n0 + r)) * DH + grp * 8);
        }
#pragma unroll
        for (int t = 0; t < 4; ++t) {
            int i = tid + t * 128;
            int col = i >> 2, grp = i & 3;
            *(uint4*)&Vs2[col][grp * 4] =
                *(const uint4*)(g_Vh + (((size_t)vtile * 128 + col) * 32) + grp * 8);
        }
        __syncthreads();

        float s[4][4] = {};
#pragma unroll
        for (int kt2 = 0; kt2 < 8; ++kt2) {
#pragma unroll
            for (int nt = 0; nt < 4; ++nt) {
                int n = nt * 8 + g;
                uint32_t b0 = Ks2[n][kt2 * 8 + t4];
                uint32_t b1 = Ks2[n][kt2 * 8 + t4 + 4];
                mma_f16(s[nt], qf[kt2], b0, b1);
            }
        }

        const int r0g = row_base + g, r1g = r0g + 8;
        const bool domask = (n0 + BN - 1 > row_base);
#pragma unroll
        for (int nt = 0; nt < 4; ++nt) {
            int c0 = n0 + nt * 8 + t4 * 2;
#pragma unroll
            for (int e = 0; e < 4; ++e) s[nt][e] *= SC;
            if (domask) {
                if (c0 > r0g)     s[nt][0] = NEG_INF;
                if (c0 + 1 > r0g) s[nt][1] = NEG_INF;
                if (c0 > r1g)     s[nt][2] = NEG_INF;
                if (c0 + 1 > r1g) s[nt][3] = NEG_INF;
            }
        }

        float mx0 = fmaxf(fmaxf(s[0][0], s[0][1]), fmaxf(s[1][0], s[1][1]));
        mx0 = fmaxf(mx0, fmaxf(fmaxf(s[2][0], s[2][1]), fmaxf(s[3][0], s[3][1])));
        float mx1 = fmaxf(fmaxf(s[0][2], s[0][3]), fmaxf(s[1][2], s[1][3]));
        mx1 = fmaxf(mx1, fmaxf(fmaxf(s[2][2], s[2][3]), fmaxf(s[3][2], s[3][3])));
        mx0 = fmaxf(mx0, __shfl_xor_sync(0xffffffffu, mx0, 1));
        mx0 = fmaxf(mx0, __shfl_xor_sync(0xffffffffu, mx0, 2));
        mx1 = fmaxf(mx1, __shfl_xor_sync(0xffffffffu, mx1, 1));
        mx1 = fmaxf(mx1, __shfl_xor_sync(0xffffffffu, mx1, 2));

        float mn0 = fmaxf(m0r, mx0), mn1 = fmaxf(m1r, mx1);
        float mu0 = fmaxf(mn0, -1e30f), mu1 = fmaxf(mn1, -1e30f);
        float al0 = ex2(m0r - mu0), al1 = ex2(m1r - mu1);
        m0r = mn0; m1r = mn1;

        float rs0 = 0.f, rs1 = 0.f;
#pragma unroll
        for (int nt = 0; nt < 4; ++nt) {
            float p00 = ex2(s[nt][0] - mu0), p01 = ex2(s[nt][1] - mu0);
            float p10 = ex2(s[nt][2] - mu1), p11 = ex2(s[nt][3] - mu1);
            rs0 += p00 + p01; rs1 += p10 + p11;
            Ps2[warp][g][nt * 4 + t4]     = packh2(p00, p01);
            Ps2[warp][g + 8][nt * 4 + t4] = packh2(p10, p11);
        }
        rs0 += __shfl_xor_sync(0xffffffffu, rs0, 1);
        rs0 += __shfl_xor_sync(0xffffffffu, rs0, 2);
        rs1 += __shfl_xor_sync(0xffffffffu, rs1, 1);
        rs1 += __shfl_xor_sync(0xffffffffu, rs1, 2);
        l0 = l0 * al0 + rs0;
        l1 = l1 * al1 + rs1;

#pragma unroll
        for (int nt = 0; nt < 16; ++nt) {
            acc[nt][0] *= al0; acc[nt][1] *= al0;
            acc[nt][2] *= al1; acc[nt][3] *= al1;
        }
        __syncwarp();

#pragma unroll
        for (int ks2 = 0; ks2 < 2; ++ks2) {
            uint32_t a[4];
            a[0] = Ps2[warp][g][ks2 * 8 + t4];
            a[1] = Ps2[warp][g + 8][ks2 * 8 + t4];
            a[2] = Ps2[warp][g][ks2 * 8 + t4 + 4];
            a[3] = Ps2[warp][g + 8][ks2 * 8 + t4 + 4];
#pragma unroll
            for (int nt = 0; nt < 16; ++nt) {
                int vn = nt * 8 + g;
                uint32_t b0 = Vs2[vn][ks2 * 8 + t4];
                uint32_t b1 = Vs2[vn][ks2 * 8 + t4 + 4];
                mma_f16(acc[nt], a, b0, b1);
            }
        }
        __syncthreads();
    }

    if (nc == 1) {
        const float inv0 = 1.0f / l0, inv1 = 1.0f / l1;
#pragma unroll
        for (int nt = 0; nt < 16; ++nt) {
            int r = row_base + g;
            int c = nt * 8 + t4 * 2;
            out[(size_t)r * DH + c]           = acc[nt][0] * inv0;
            out[(size_t)r * DH + c + 1]       = acc[nt][1] * inv0;
            out[(size_t)(r + 8) * DH + c]     = acc[nt][2] * inv1;
            out[(size_t)(r + 8) * DH + c + 1] = acc[nt][3] * inv1;
        }
        return;
    }

    // write unnormalized partials + stats
    {
        const int pslot = qt * MAXC + ch;
        float* Op = g_Opart + (size_t)pslot * 64 * DH;
        const int lr0 = warp * 16 + g, lr1 = lr0 + 8;
#pragma unroll
        for (int nt = 0; nt < 16; ++nt) {
            int c = nt * 8 + t4 * 2;
            Op[(size_t)lr0 * DH + c]     = acc[nt][0];
            Op[(size_t)lr0 * DH + c + 1] = acc[nt][1];
            Op[(size_t)lr1 * DH + c]     = acc[nt][2];
            Op[(size_t)lr1 * DH + c + 1] = acc[nt][3];
        }
        if (t4 == 0) {
            g_mpart[pslot * 64 + lr0] = m0r;
            g_lpart[pslot * 64 + lr0] = l0;
            g_mpart[pslot * 64 + lr1] = m1r;
            g_lpart[pslot * 64 + lr1] = l1;
        }
    }

    // last-block combine (threadFenceReduction pattern)
    __threadfence();
    __syncthreads();
    if (tid == 0) {
        int old = atomicAdd(&g_cnt[qt], 1);
        isLast = (old == nc - 1);
    }
    __syncthreads();
    if (!isLast) return;
    __threadfence();

    // this CTA merges all nc partials for rows [qm0, qm0+64)
#pragma unroll 4
    for (int it = 0; it < 16; ++it) {
        int idx = tid + it * 128;          // 0..2047
        int lr  = idx >> 5;                 // 0..63
        int c4  = (idx & 31) * 4;
        float M = -1e30f;
        for (int c = 0; c < nc; ++c)
            M = fmaxf(M, g_mpart[(qt * MAXC + c) * 64 + lr]);
        float l = 0.f, ox = 0.f, oy = 0.f, oz = 0.f, ow = 0.f;
        for (int c = 0; c < nc; ++c) {
            int ps = qt * MAXC + c;
            float a = ex2(g_mpart[ps * 64 + lr] - M);
            l += a * g_lpart[ps * 64 + lr];
            float4 v = *(const float4*)&g_Opart[((size_t)ps * 64 + lr) * DH + c4];
            ox += a * v.x; oy += a * v.y; oz += a * v.z; ow += a * v.w;
        }
        float inv = 1.0f / l;
        float4 o = { ox * inv, oy * inv, oz * inv, ow * inv };
        *(float4*)&out[(size_t)(qm0 + lr) * DH + c4] = o;
    }
    if (tid == 0) g_cnt[qt] = 0;   // reset for next graph replay
}

// ---------------------------------------------------------------------------

extern "C" void kernel_launch(void* const* d_in, const int* in_sizes, int n_in,
                              void* d_out, int out_size) {
    (void)in_sizes; (void)n_in; (void)out_size;
    const float* xq = (const float*)d_in[0];
    const float* xk = (const float*)d_in[1];
    const float* xv = (const float*)d_in[2];
    const float* wq = (const float*)d_in[3];
    const float* bq = (const float*)d_in[4];
    const float* wk = (const float*)d_in[5];
    const float* bk = (const float*)d_in[6];
    const float* wv = (const float*)d_in[7];
    const float* bv = (const float*)d_in[8];
    float* out = (float*)d_out;

    cudaFuncSetAttribute(proj_kernel, cudaFuncAttributeMaxDynamicSharedMemorySize, PJ_SMEM);

    prep_w<<<768, 256>>>(wq, wk, wv);
    proj_kernel<<<dim3(SEQ / 32, 3), 128, PJ_SMEM>>>(xq, xk, xv, bq, bk, bv);
    attn_kernel<<<dim3(SEQ / BM, MAXC), 128>>>(out);
}

// round 17
// speedup vs baseline: 1.2095x; 1.2095x over previous
#include <cuda_runtime.h>
#include <cuda_fp16.h>
#include <cstdint>
#include <cstddef>

#define SEQ     4096
#define DMODEL  2048
#define DH      128
#define CHUNK   512          // keys per split-KV work unit
#define MAXC    8            // max chunks per q-tile (4096/512)

// Scratch (allocation-free rule: __device__ globals)
__device__ __align__(16) __half g_Qh[SEQ * DH];          // [row][col]
__device__ __align__(16) __half g_Kh[SEQ * DH];          // [row][col]
__device__ __align__(16) __half g_Vh[SEQ * DH];          // [tile32][col][key-in-tile]
// W as fp16 m16n8k16 b-fragment pairs:
// [mat][kb16 0..127][n 0..127][t4 0..3][2]  (u32 = half2 units)
__device__ __align__(16) uint32_t g_Whf[3 * 128 * 128 * 8];
// split-KV partials
__device__ float g_Opart[64 * MAXC * 64 * DH];
__device__ float g_mpart[64 * MAXC * 64];
__device__ float g_lpart[64 * MAXC * 64];

__device__ __forceinline__ float ex2(float x) {
    float y;
    asm("ex2.approx.ftz.f32 %0, %1;" : "=f"(y) : "f"(x));
    return y;
}
__device__ __forceinline__ void mma_f16(float d[4], const uint32_t a[4],
                                        uint32_t b0, uint32_t b1) {
    asm volatile(
        "mma.sync.aligned.m16n8k16.row.col.f32.f16.f16.f32 "
        "{%0,%1,%2,%3},{%4,%5,%6,%7},{%8,%9},{%0,%1,%2,%3};\n"
        : "+f"(d[0]), "+f"(d[1]), "+f"(d[2]), "+f"(d[3])
        : "r"(a[0]), "r"(a[1]), "r"(a[2]), "r"(a[3]), "r"(b0), "r"(b1));
}
__device__ __forceinline__ void cpa16(uint32_t dst, const void* src) {
    asm volatile("cp.async.cg.shared.global [%0], [%1], 16;\n" :: "r"(dst), "l"(src));
}
__device__ __forceinline__ void cp_commit() {
    asm volatile("cp.async.commit_group;\n" ::);
}
template <int N>
__device__ __forceinline__ void cp_wait() {
    asm volatile("cp.async.wait_group %0;\n" :: "n"(N));
}
__device__ __forceinline__ uint32_t s2u(const void* p) {
    return (uint32_t)__cvta_generic_to_shared(p);
}
__device__ __forceinline__ uint32_t packh2(float x, float y) {
    __half2 h = __floats2half2_rn(x, y);
    return *(uint32_t*)&h;
}

// ---------------------------------------------------------------------------
// prep_w v2: W -> fp16 k16 b-fragment pairs, float2 loads (2xLDG.64/thread).
// ---------------------------------------------------------------------------
__global__ __launch_bounds__(256)
void prep_w(const float* __restrict__ wq, const float* __restrict__ wk,
            const float* __restrict__ wv) {
    int id = blockIdx.x * 256 + threadIdx.x;       // 0 .. 196607
    int mat = id / (128 * 128 * 4);
    int rem = id % (128 * 128 * 4);
    int kb = rem >> 9;
    int rem2 = rem & 511;
    int n = rem2 >> 2;
    int t4 = rem2 & 3;
    const float* W = (mat == 0) ? wq : (mat == 1) ? wk : wv;
    const float* wr = W + (size_t)n * DMODEL + kb * 16;
    float2 lo = *(const float2*)(wr + 2 * t4);
    float2 hi = *(const float2*)(wr + 8 + 2 * t4);
    uint2 o;
    o.x = packh2(lo.x, lo.y);
    o.y = packh2(hi.x, hi.y);
    *(uint2*)&g_Whf[(((size_t)mat * 128 + kb) * 128 + n) * 8 + t4 * 2] = o;
}

// ---------------------------------------------------------------------------
// Projection v7 (byte-identical to the 83.0 build): fp16 m16n8k16, full K,
// fused bias+pack epilogue, 64(M) x 128(N), 128 thr, occ 4, grid (64, 3).
// ---------------------------------------------------------------------------
#define PJ_DEPTH 4
#define XSTRH    24                      // fp32 words per X smem row
#define XS_FL    (64 * XSTRH)            // 1536 floats / stage
#define WS_U32   (128 * 8)               // 1024 u32 / stage
#define PJ_SMEM  (PJ_DEPTH * (XS_FL * 4 + WS_U32 * 4))   // 40960 B

__global__ __launch_bounds__(128, 4)
void proj_kernel(const float* __restrict__ xq, const float* __restrict__ xk,
                 const float* __restrict__ xv,
                 const float* __restrict__ bq, const float* __restrict__ bk,
                 const float* __restrict__ bv) {
    extern __shared__ float sm[];
    float*    Xs = sm;                                   // [4][64][24]
    uint32_t* Wh = (uint32_t*)(sm + PJ_DEPTH * XS_FL);   // [4][128][8]

    const int mat = blockIdx.y;
    const float* X    = (mat == 0) ? xq : (mat == 1) ? xk : xv;
    const float* bias = (mat == 0) ? bq : (mat == 1) ? bk : bv;

    const int tid  = threadIdx.x;
    const int warp = tid >> 5, lane = tid & 31;
    const int g    = lane >> 2, t4 = lane & 3;
    const int wm   = warp >> 1;   // 0..1 : 32 M-rows each
    const int wn   = warp & 1;    // 0..1 : 64 N-cols each
    const int m0   = blockIdx.x * 64;

    const uint32_t* gwh = g_Whf + (size_t)mat * 128 * 128 * 8;

    float acc[2][8][4] = {};

    auto issue = [&](int sidx) {
        const int s  = sidx & (PJ_DEPTH - 1);
        const int k0 = sidx * 16;
#pragma unroll
        for (int t = 0; t < 2; ++t) {
            int i = tid + t * 128;
            int r = i >> 2, c4 = (i & 3) * 4;
            cpa16(s2u(&Xs[(s * 64 + r) * XSTRH + c4]),
                  X + (size_t)(m0 + r) * DMODEL + k0 + c4);
        }
#pragma unroll
        for (int t = 0; t < 2; ++t) {
            int i = tid + t * 128;
            int n = i >> 1, half = i & 1;
            cpa16(s2u(&Wh[(s * 128 + n) * 8 + half * 4]),
                  gwh + (((size_t)sidx) * 128 + n) * 8 + half * 4);
        }
        cp_commit();
    };

    issue(0); issue(1); issue(2);

    const int NK = DMODEL / 16;   // 128 stages
    for (int i = 0; i < NK; ++i) {
        if (i + 3 < NK) { cp_wait<2>(); } else { cp_wait<0>(); }
        __syncthreads();
        if (i + 3 < NK) issue(i + 3);

        const int s = i & (PJ_DEPTH - 1);
        const float*    Xc = &Xs[s * XS_FL];
        const uint32_t* Wc = &Wh[s * WS_U32];

        uint32_t a[2][4];
#pragma unroll
        for (int mt = 0; mt < 2; ++mt) {
            int r = wm * 32 + mt * 16 + g;
            float2 x0 = *(const float2*)&Xc[r * XSTRH + 2 * t4];
            float2 x1 = *(const float2*)&Xc[(r + 8) * XSTRH + 2 * t4];
            float2 x2 = *(const float2*)&Xc[r * XSTRH + 2 * t4 + 8];
            float2 x3 = *(const float2*)&Xc[(r + 8) * XSTRH + 2 * t4 + 8];
            a[mt][0] = packh2(x0.x, x0.y);
            a[mt][1] = packh2(x1.x, x1.y);
            a[mt][2] = packh2(x2.x, x2.y);
            a[mt][3] = packh2(x3.x, x3.y);
        }
#pragma unroll
        for (int nt = 0; nt < 8; ++nt) {
            int n = wn * 64 + nt * 8 + g;
            uint2 b = *(const uint2*)&Wc[n * 8 + t4 * 2];   // LDS.64, conflict-free
            mma_f16(acc[0][nt], a[0], b.x, b.y);
            mma_f16(acc[1][nt], a[1], b.x, b.y);
        }
    }

    // fused epilogue: bias + fp16; Q/K natural layout, V transposed per tile
    if (mat < 2) {
        __half* dst = (mat == 0) ? g_Qh : g_Kh;
#pragma unroll
        for (int mt = 0; mt < 2; ++mt) {
#pragma unroll
            for (int nt = 0; nt < 8; ++nt) {
                int r = m0 + wm * 32 + mt * 16 + g;
                int c = wn * 64 + nt * 8 + t4 * 2;
                float b0 = bias[c], b1 = bias[c + 1];
                *(uint32_t*)(dst + (size_t)r * DH + c) =
                    packh2(acc[mt][nt][0] + b0, acc[mt][nt][1] + b1);
                *(uint32_t*)(dst + (size_t)(r + 8) * DH + c) =
                    packh2(acc[mt][nt][2] + b0, acc[mt][nt][3] + b1);
            }
        }
    } else {
#pragma unroll
        for (int mt = 0; mt < 2; ++mt) {
#pragma unroll
            for (int nt = 0; nt < 8; ++nt) {
                int r = m0 + wm * 32 + mt * 16 + g;
                int c = wn * 64 + nt * 8 + t4 * 2;
                float b0 = bias[c], b1 = bias[c + 1];
                size_t base = (size_t)(r >> 5) * (DH * 32);
                int lr = r & 31;
                g_Vh[base + (size_t)c * 32 + lr]            = __float2half_rn(acc[mt][nt][0] + b0);
                g_Vh[base + (size_t)(c + 1) * 32 + lr]      = __float2half_rn(acc[mt][nt][1] + b1);
                g_Vh[base + (size_t)c * 32 + lr + 8]        = __float2half_rn(acc[mt][nt][2] + b0);
                g_Vh[base + (size_t)(c + 1) * 32 + lr + 8]  = __float2half_rn(acc[mt][nt][3] + b1);
            }
        }
    }
}

// ---------------------------------------------------------------------------
// Split-KV causal flash attention (byte-identical to the 83.0 build).
// ---------------------------------------------------------------------------
#define BM 64
#define BN 32

__global__ __launch_bounds__(128, 2)
void attn_kernel(float* __restrict__ out) {
    const int qt = blockIdx.x;
    const int ch = blockIdx.y;
    const int nc = (qt >> 3) + 1;
    if (ch >= nc) return;

    __shared__ uint32_t Ks2[32][68];
    __shared__ uint32_t Vs2[128][20];
    __shared__ uint32_t Ps2[4][16][20];

    const int tid  = threadIdx.x;
    const int warp = tid >> 5, lane = tid & 31;
    const int g    = lane >> 2, t4 = lane & 3;
    const int qm0  = qt * BM;
    const int row_base = qm0 + warp * 16;
    const float NEG_INF = __int_as_float(0xff800000u);
    const float SC = 0.02209708691207961f * 1.4426950408889634f;

    const int kstart = ch * CHUNK;
    const int kend   = min(kstart + CHUNK, qm0 + BM);
    const int ntiles = (kend - kstart) / BN;

    const uint32_t* qh32 = (const uint32_t*)g_Qh;
    uint32_t qf[8][4];
    {
        const int r0 = row_base + g, r1 = r0 + 8;
#pragma unroll
        for (int kt2 = 0; kt2 < 8; ++kt2) {
            qf[kt2][0] = qh32[(size_t)r0 * 64 + kt2 * 8 + t4];
            qf[kt2][1] = qh32[(size_t)r1 * 64 + kt2 * 8 + t4];
            qf[kt2][2] = qh32[(size_t)r0 * 64 + kt2 * 8 + t4 + 4];
            qf[kt2][3] = qh32[(size_t)r1 * 64 + kt2 * 8 + t4 + 4];
        }
    }

    float acc[16][4] = {};
    float m0r = NEG_INF, m1r = NEG_INF;
    float l0 = 0.f, l1 = 0.f;

    for (int j = 0; j < ntiles; ++j) {
        const int n0 = kstart + j * BN;
        const int vtile = n0 >> 5;

#pragma unroll
        for (int t = 0; t < 4; ++t) {
            int i = tid + t * 128;
            int r = i >> 4, grp = i & 15;
            *(uint4*)&Ks2[r][grp * 4] =
                *(const uint4*)(g_Kh + ((size_t)(n0 + r)) * DH + grp * 8);
        }
#pragma unroll
        for (int t = 0; t < 4; ++t) {
            int i = tid + t * 128;
            int col = i >> 2, grp = i & 3;
            *(uint4*)&Vs2[col][grp * 4] =
                *(const uint4*)(g_Vh + (((size_t)vtile * 128 + col) * 32) + grp * 8);
        }
        __syncthreads();

        float s[4][4] = {};
#pragma unroll
        for (int kt2 = 0; kt2 < 8; ++kt2) {
#pragma unroll
            for (int nt = 0; nt < 4; ++nt) {
                int n = nt * 8 + g;
                uint32_t b0 = Ks2[n][kt2 * 8 + t4];
                uint32_t b1 = Ks2[n][kt2 * 8 + t4 + 4];
                mma_f16(s[nt], qf[kt2], b0, b1);
            }
        }

        const int r0g = row_base + g, r1g = r0g + 8;
        const bool domask = (n0 + BN - 1 > row_base);
#pragma unroll
        for (int nt = 0; nt < 4; ++nt) {
            int c0 = n0 + nt * 8 + t4 * 2;
#pragma unroll
            for (int e = 0; e < 4; ++e) s[nt][e] *= SC;
            if (domask) {
                if (c0 > r0g)     s[nt][0] = NEG_INF;
                if (c0 + 1 > r0g) s[nt][1] = NEG_INF;
                if (c0 > r1g)     s[nt][2] = NEG_INF;
                if (c0 + 1 > r1g) s[nt][3] = NEG_INF;
            }
        }

        float mx0 = fmaxf(fmaxf(s[0][0], s[0][1]), fmaxf(s[1][0], s[1][1]));
        mx0 = fmaxf(mx0, fmaxf(fmaxf(s[2][0], s[2][1]), fmaxf(s[3][0], s[3][1])));
        float mx1 = fmaxf(fmaxf(s[0][2], s[0][3]), fmaxf(s[1][2], s[1][3]));
        mx1 = fmaxf(mx1, fmaxf(fmaxf(s[2][2], s[2][3]), fmaxf(s[3][2], s[3][3])));
        mx0 = fmaxf(mx0, __shfl_xor_sync(0xffffffffu, mx0, 1));
        mx0 = fmaxf(mx0, __shfl_xor_sync(0xffffffffu, mx0, 2));
        mx1 = fmaxf(mx1, __shfl_xor_sync(0xffffffffu, mx1, 1));
        mx1 = fmaxf(mx1, __shfl_xor_sync(0xffffffffu, mx1, 2));

        float mn0 = fmaxf(m0r, mx0), mn1 = fmaxf(m1r, mx1);
        float mu0 = fmaxf(mn0, -1e30f), mu1 = fmaxf(mn1, -1e30f);
        float al0 = ex2(m0r - mu0), al1 = ex2(m1r - mu1);
        m0r = mn0; m1r = mn1;

        float rs0 = 0.f, rs1 = 0.f;
#pragma unroll
        for (int nt = 0; nt < 4; ++nt) {
            float p00 = ex2(s[nt][0] - mu0), p01 = ex2(s[nt][1] - mu0);
            float p10 = ex2(s[nt][2] - mu1), p11 = ex2(s[nt][3] - mu1);
            rs0 += p00 + p01; rs1 += p10 + p11;
            Ps2[warp][g][nt * 4 + t4]     = packh2(p00, p01);
            Ps2[warp][g + 8][nt * 4 + t4] = packh2(p10, p11);
        }
        rs0 += __shfl_xor_sync(0xffffffffu, rs0, 1);
        rs0 += __shfl_xor_sync(0xffffffffu, rs0, 2);
        rs1 += __shfl_xor_sync(0xffffffffu, rs1, 1);
        rs1 += __shfl_xor_sync(0xffffffffu, rs1, 2);
        l0 = l0 * al0 + rs0;
        l1 = l1 * al1 + rs1;

#pragma unroll
        for (int nt = 0; nt < 16; ++nt) {
            acc[nt][0] *= al0; acc[nt][1] *= al0;
            acc[nt][2] *= al1; acc[nt][3] *= al1;
        }
        __syncwarp();

#pragma unroll
        for (int ks2 = 0; ks2 < 2; ++ks2) {
            uint32_t a[4];
            a[0] = Ps2[warp][g][ks2 * 8 + t4];
            a[1] = Ps2[warp][g + 8][ks2 * 8 + t4];
            a[2] = Ps2[warp][g][ks2 * 8 + t4 + 4];
            a[3] = Ps2[warp][g + 8][ks2 * 8 + t4 + 4];
#pragma unroll
            for (int nt = 0; nt < 16; ++nt) {
                int vn = nt * 8 + g;
                uint32_t b0 = Vs2[vn][ks2 * 8 + t4];
                uint32_t b1 = Vs2[vn][ks2 * 8 + t4 + 4];
                mma_f16(acc[nt], a, b0, b1);
            }
        }
        __syncthreads();
    }

    if (nc == 1) {
        const float inv0 = 1.0f / l0, inv1 = 1.0f / l1;
#pragma unroll
        for (int nt = 0; nt < 16; ++nt) {
            int r = row_base + g;
            int c = nt * 8 + t4 * 2;
            out[(size_t)r * DH + c]           = acc[nt][0] * inv0;
            out[(size_t)r * DH + c + 1]       = acc[nt][1] * inv0;
            out[(size_t)(r + 8) * DH + c]     = acc[nt][2] * inv1;
            out[(size_t)(r + 8) * DH + c + 1] = acc[nt][3] * inv1;
        }
    } else {
        const int pslot = qt * MAXC + ch;
        float* Op = g_Opart + (size_t)pslot * 64 * DH;
        const int lr0 = warp * 16 + g, lr1 = lr0 + 8;
#pragma unroll
        for (int nt = 0; nt < 16; ++nt) {
            int c = nt * 8 + t4 * 2;
            Op[(size_t)lr0 * DH + c]     = acc[nt][0];
            Op[(size_t)lr0 * DH + c + 1] = acc[nt][1];
            Op[(size_t)lr1 * DH + c]     = acc[nt][2];
            Op[(size_t)lr1 * DH + c + 1] = acc[nt][3];
        }
        if (t4 == 0) {
            g_mpart[pslot * 64 + lr0] = m0r;
            g_lpart[pslot * 64 + lr0] = l0;
            g_mpart[pslot * 64 + lr1] = m1r;
            g_lpart[pslot * 64 + lr1] = l1;
        }
    }
}

// ---------------------------------------------------------------------------
// Combine v3: rows 512..4095; 8 rows/block, 32 thr/row. All nc stat loads
// and all nc Opart float4 loads are prefetched into registers back-to-back
// (predicated unroll over MAXC) before any dependent math -> MLP 8-24.
// ---------------------------------------------------------------------------
__global__ __launch_bounds__(256)
void combine_kernel(float* __restrict__ out) {
    const int lrow = threadIdx.x >> 5;         // 0..7
    const int c4   = (threadIdx.x & 31) * 4;   // column group
    const int row  = 512 + blockIdx.x * 8 + lrow;
    const int qt   = row >> 6;
    const int nc   = (qt >> 3) + 1;
    const int lr   = row & 63;

    float ms[MAXC], ls[MAXC];
    float4 vs[MAXC];
#pragma unroll
    for (int c = 0; c < MAXC; ++c) {
        if (c < nc) {
            int ps = qt * MAXC + c;
            ms[c] = g_mpart[ps * 64 + lr];
            ls[c] = g_lpart[ps * 64 + lr];
            vs[c] = *(const float4*)&g_Opart[((size_t)ps * 64 + lr) * DH + c4];
        }
    }

    float M = -1e30f;
#pragma unroll
    for (int c = 0; c < MAXC; ++c)
        if (c < nc) M = fmaxf(M, ms[c]);

    float l = 0.f, ox = 0.f, oy = 0.f, oz = 0.f, ow = 0.f;
#pragma unroll
    for (int c = 0; c < MAXC; ++c) {
        if (c < nc) {
            float a = ex2(ms[c] - M);
            l += a * ls[c];
            ox += a * vs[c].x; oy += a * vs[c].y;
            oz += a * vs[c].z; ow += a * vs[c].w;
        }
    }
    float inv = 1.0f / l;
    float4 o = { ox * inv, oy * inv, oz * inv, ow * inv };
    *(float4*)&out[(size_t)row * DH + c4] = o;
}

// ---------------------------------------------------------------------------

extern "C" void kernel_launch(void* const* d_in, const int* in_sizes, int n_in,
                              void* d_out, int out_size) {
    (void)in_sizes; (void)n_in; (void)out_size;
    const float* xq = (const float*)d_in[0];
    const float* xk = (const float*)d_in[1];
    const float* xv = (const float*)d_in[2];
    const float* wq = (const float*)d_in[3];
    const float* bq = (const float*)d_in[4];
    const float* wk = (const float*)d_in[5];
    const float* bk = (const float*)d_in[6];
    const float* wv = (const float*)d_in[7];
    const float* bv = (const float*)d_in[8];
    float* out = (float*)d_out;

    cudaFuncSetAttribute(proj_kernel, cudaFuncAttributeMaxDynamicSharedMemorySize, PJ_SMEM);

    prep_w<<<768, 256>>>(wq, wk, wv);
    proj_kernel<<<dim3(SEQ / 64, 3), 128, PJ_SMEM>>>(xq, xk, xv, bq, bk, bv);
    attn_kernel<<<dim3(SEQ / BM, MAXC), 128>>>(out);
    combine_kernel<<<(SEQ - 512) / 8, 256>>>(out);
}